// round 16
// baseline (speedup 1.0000x reference)
#include <cuda_runtime.h>
#include <cuda_fp16.h>
#include <mma.h>
#include <math.h>

using namespace nvcuda;

#define NN 50000
#define EE 800000
#define F1 128
#define HEADS 8
#define HID 16
#define OUTC 16
#define NEG_SLOPE 0.2f
#define MAXDEG 64

#define LDA 136
#define LDB 136
#define LDC 132
#define ROWS_PER_BLK 64
#define SMEM_B_BYTES (F1 * LDB * 2)
#define SMEM_AC_BYTES (ROWS_PER_BLK * LDC * 4)
#define SMEM_TOTAL (SMEM_B_BYTES + SMEM_AC_BYTES)

__device__ __forceinline__ int pack_h2(float a, float b) {
    __half2 h = __floats2half2_rn(a, b);
    return *(int*)&h;
}

// ---------------- scratch ----------------
__device__ __align__(16) __half g_h1h[NN * F1];
__device__ __align__(16) float  g_out1[NN * F1];
__device__ float g_als1[NN * HEADS];
__device__ float g_ald1[NN * HEADS];
__device__ __align__(16) __half g_h2h[NN * OUTC];
__device__ float g_als2[NN];
__device__ float g_ald2[NN];
__device__ int   g_cnt[NN];
__device__ int   g_csr[NN * MAXDEG];
__device__ __align__(16) __half g_W1h[F1 * F1];
__device__ __align__(16) __half g_wq[(size_t)NN * MAXDEG * HEADS]; // [d][slot][h]
__device__ float g_invden1[NN * HEADS];

// ---------------- init ----------------
__global__ void k_init(const float* __restrict__ W1) {
    int i = blockIdx.x * blockDim.x + threadIdx.x;
    if (i < F1 * F1) g_W1h[i] = __float2half(W1[i]);
    if (i < NN) {
        g_cnt[i] = 1;
        g_csr[i * MAXDEG] = i;
    }
}

__global__ void k_fill(const int* __restrict__ ei) {
    int base = (blockIdx.x * blockDim.x + threadIdx.x) * 4;
    if (base >= EE) return;
#pragma unroll
    for (int k = 0; k < 4; k++) {
        int e = base + k;
        if (e < EE) {
            int s = ei[e], d = ei[EE + e];
            int pos = atomicAdd(&g_cnt[d], 1);
            if (pos < MAXDEG) g_csr[d * MAXDEG + pos] = s;
        }
    }
}

// ---------------- layer 1: wmma GEMM + cheap epilogue ----------------
__global__ void __launch_bounds__(256) k_gemm1(const float* __restrict__ x,
                                               const float* __restrict__ as1,
                                               const float* __restrict__ ad1) {
    extern __shared__ __align__(16) char dsm[];
    __half* Bs = (__half*)dsm;
    char* ACbuf = dsm + SMEM_B_BYTES;
    __half* As = (__half*)ACbuf;
    float*  Cs = (float*)ACbuf;
    __shared__ float s_as[F1], s_ad[F1];

    int t = threadIdx.x;
    int rows = blockIdx.x * ROWS_PER_BLK;

    if (t < F1) s_as[t] = as1[t];
    else        s_ad[t - F1] = ad1[t - F1];

#pragma unroll
    for (int i = 0; i < 8; i++) {
        int idx = t + 256 * i;
        int le  = idx * 4;
        int r   = le >> 7;
        int c   = le & 127;
        float4 f = {0.f, 0.f, 0.f, 0.f};
        if (rows + r < NN) f = ((const float4*)x)[rows * 32 + idx];
        __half2* dst = (__half2*)(As + r * LDA + c);
        dst[0] = __floats2half2_rn(f.x, f.y);
        dst[1] = __floats2half2_rn(f.z, f.w);
    }
#pragma unroll
    for (int i = 0; i < 8; i++) {
        int idx = t + 256 * i;
        int le  = idx * 8;
        int k   = le >> 7;
        int n   = le & 127;
        *(int4*)(Bs + k * LDB + n) = ((const int4*)g_W1h)[idx];
    }
    __syncthreads();

    int w = t >> 5;
    wmma::fragment<wmma::accumulator, 16, 16, 16, float> c0, c1, c2, c3;
    wmma::fill_fragment(c0, 0.f);
    wmma::fill_fragment(c1, 0.f);
    wmma::fill_fragment(c2, 0.f);
    wmma::fill_fragment(c3, 0.f);
#pragma unroll
    for (int k = 0; k < 8; k++) {
        wmma::fragment<wmma::matrix_a, 16, 16, 16, __half, wmma::row_major> a0, a1, a2, a3;
        wmma::fragment<wmma::matrix_b, 16, 16, 16, __half, wmma::row_major> b;
        wmma::load_matrix_sync(b, Bs + (k * 16) * LDB + w * 16, LDB);
        wmma::load_matrix_sync(a0, As + (0 * 16) * LDA + k * 16, LDA);
        wmma::load_matrix_sync(a1, As + (1 * 16) * LDA + k * 16, LDA);
        wmma::load_matrix_sync(a2, As + (2 * 16) * LDA + k * 16, LDA);
        wmma::load_matrix_sync(a3, As + (3 * 16) * LDA + k * 16, LDA);
        wmma::mma_sync(c0, a0, b, c0);
        wmma::mma_sync(c1, a1, b, c1);
        wmma::mma_sync(c2, a2, b, c2);
        wmma::mma_sync(c3, a3, b, c3);
    }
    __syncthreads();
    wmma::store_matrix_sync(Cs + (0 * 16) * LDC + w * 16, c0, LDC, wmma::mem_row_major);
    wmma::store_matrix_sync(Cs + (1 * 16) * LDC + w * 16, c1, LDC, wmma::mem_row_major);
    wmma::store_matrix_sync(Cs + (2 * 16) * LDC + w * 16, c2, LDC, wmma::mem_row_major);
    wmma::store_matrix_sync(Cs + (3 * 16) * LDC + w * 16, c3, LDC, wmma::mem_row_major);
    __syncthreads();

    {
        int row = t >> 2;
        int col0 = (t & 3) * 32;
        int grow = rows + row;
        if (grow < NN) {
            const float* src = Cs + row * LDC + col0;
            __half* dst = g_h1h + grow * F1 + col0;
#pragma unroll
            for (int i = 0; i < 4; i++) {
                float4 a = *(const float4*)(src + i * 8);
                float4 b = *(const float4*)(src + i * 8 + 4);
                int4 pk;
                pk.x = pack_h2(a.x, a.y);
                pk.y = pack_h2(a.z, a.w);
                pk.z = pack_h2(b.x, b.y);
                pk.w = pack_h2(b.z, b.w);
                *(int4*)(dst + i * 8) = pk;
            }
        }
    }

#pragma unroll
    for (int pp = 0; pp < 2; pp++) {
        int pair = t + pp * 256;
        int row = pair >> 3, h = pair & 7;
        int grow = rows + row;
        const float* cr = Cs + row * LDC + h * 16;
        const float* av = s_as + h * 16;
        const float* dv = s_ad + h * 16;
        float p = 0.f, q = 0.f;
#pragma unroll
        for (int i = 0; i < 4; i++) {
            float4 v = *(const float4*)(cr + i * 4);
            float4 a = *(const float4*)(av + i * 4);
            float4 dd = *(const float4*)(dv + i * 4);
            p = fmaf(v.x, a.x, p);  q = fmaf(v.x, dd.x, q);
            p = fmaf(v.y, a.y, p);  q = fmaf(v.y, dd.y, q);
            p = fmaf(v.z, a.z, p);  q = fmaf(v.z, dd.z, q);
            p = fmaf(v.w, a.w, p);  q = fmaf(v.w, dd.w, q);
        }
        if (grow < NN) {
            g_als1[grow * HEADS + h] = p;
            g_ald1[grow * HEADS + h] = q;
        }
    }
}

// ---------------- layer 1: per-edge weights + inv-denominator ----------------
// 256 threads = 64 slots x 4 head-pairs. Thread handles exactly ONE slot.
__global__ void __launch_bounds__(256) k_w() {
    int d = blockIdx.x;
    int t = threadIdx.x;
    int cnt = min(g_cnt[d], MAXDEG);
    const int* bucket = g_csr + d * MAXDEG;
    int slot = t >> 2;                   // 0..63 (one slot per thread)
    int h0 = (t & 3) * 2;                // 0,2,4,6
    float ald0 = g_ald1[d * HEADS + h0];
    float ald1v = g_ald1[d * HEADS + h0 + 1];
    float a0 = 0.f, a1 = 0.f;
    if (slot < cnt) {
        int src = bucket[slot];
        float v0 = g_als1[src * HEADS + h0] + ald0;
        v0 = fmaxf(v0, NEG_SLOPE * v0);
        a0 = __expf(v0);
        float v1 = g_als1[src * HEADS + h0 + 1] + ald1v;
        v1 = fmaxf(v1, NEG_SLOPE * v1);
        a1 = __expf(v1);
    }
    *(__half2*)(g_wq + (size_t)d * (MAXDEG * HEADS) + slot * HEADS + h0) = __floats2half2_rn(a0, a1);
    // reduce over the 8 slots within each warp (lanes with same lane&3)
    float sum0 = a0, sum1 = a1;
#pragma unroll
    for (int off = 4; off < 32; off <<= 1) {
        sum0 += __shfl_xor_sync(0xffffffffu, sum0, off);
        sum1 += __shfl_xor_sync(0xffffffffu, sum1, off);
    }
    __shared__ float sred[8][4][2];
    int lane = t & 31, wp = t >> 5;
    if (lane < 4) { sred[wp][lane][0] = sum0; sred[wp][lane][1] = sum1; }
    __syncthreads();
    if (t < HEADS) {
        float tot = 0.f;
#pragma unroll
        for (int w = 0; w < 8; w++) tot += sred[w][t >> 1][t & 1];
        g_invden1[d * HEADS + t] = 1.f / tot;
    }
}

// ---------------- layer 1: aggregation, warp/node, branch-free chunks of 16 ----------------
__global__ void k_agg1(const float* __restrict__ b1) {
    int warp = threadIdx.x >> 5;
    int lane = threadIdx.x & 31;
    int d = blockIdx.x * 8 + warp;
    if (d >= NN) return;
    int h = lane >> 2;
    int cnt = min(g_cnt[d], MAXDEG);
    int cnt16 = (cnt + 15) & ~15;
    const int* bucket = g_csr + d * MAXDEG;
    const __half* wrow = g_wq + (size_t)d * (MAXDEG * HEADS) + h;
    const __half* hbase = g_h1h + lane * 4;
    float4 acc = {0.f, 0.f, 0.f, 0.f};
    for (int i0 = 0; i0 < cnt16; i0 += 16) {
        int s = bucket[i0 + (lane & 15)];
        const __half* wchunk = wrow + i0 * HEADS;
#pragma unroll
        for (int j = 0; j < 16; j++) {
            int sj = __shfl_sync(0xffffffffu, s, j);
            unsigned su = min((unsigned)sj, (unsigned)(NN - 1));  // padded slots have w=0
            float w = __half2float(wchunk[j * HEADS]);
            uint2 hv = *(const uint2*)(hbase + ((size_t)su << 7));
            float2 f0 = __half22float2(*(const __half2*)&hv.x);
            float2 f1 = __half22float2(*(const __half2*)&hv.y);
            acc.x = fmaf(w, f0.x, acc.x);
            acc.y = fmaf(w, f0.y, acc.y);
            acc.z = fmaf(w, f1.x, acc.z);
            acc.w = fmaf(w, f1.y, acc.w);
        }
    }
    float inv = g_invden1[d * HEADS + h];
    float4 bv = *(const float4*)(b1 + lane * 4);
    float4 o;
    o.x = acc.x * inv + bv.x;
    o.y = acc.y * inv + bv.y;
    o.z = acc.z * inv + bv.z;
    o.w = acc.w * inv + bv.w;
    o.x = o.x > 0.f ? o.x : expm1f(o.x);
    o.y = o.y > 0.f ? o.y : expm1f(o.y);
    o.z = o.z > 0.f ? o.z : expm1f(o.z);
    o.w = o.w > 0.f ? o.w : expm1f(o.w);
    *(float4*)(g_out1 + d * F1 + lane * 4) = o;
}

// ---------------- layer 2: GEMM ----------------
__global__ void k_gemm2(const float* __restrict__ W2,
                        const float* __restrict__ as2, const float* __restrict__ ad2) {
    int t = threadIdx.x;
    int rbase = blockIdx.x * 16;
    __shared__ float4 sh[16][32];
    __shared__ float ws[F1][OUTC];
    const float4* src = (const float4*)(g_out1 + rbase * F1);
    ((float4*)sh)[t]       = src[t];
    ((float4*)sh)[t + 256] = src[t + 256];
#pragma unroll
    for (int i = t; i < F1 * OUTC; i += 256) ws[i >> 4][i & 15] = W2[i];
    __syncthreads();
    int r_loc = t >> 4, c = t & 15;
    float acc = 0.f;
#pragma unroll 8
    for (int k4 = 0; k4 < 32; k4++) {
        float4 hv = sh[r_loc][k4];
        acc = fmaf(hv.x, ws[k4 * 4 + 0][c], acc);
        acc = fmaf(hv.y, ws[k4 * 4 + 1][c], acc);
        acc = fmaf(hv.z, ws[k4 * 4 + 2][c], acc);
        acc = fmaf(hv.w, ws[k4 * 4 + 3][c], acc);
    }
    int r = rbase + r_loc;
    g_h2h[r * OUTC + c] = __float2half(acc);
    float p = acc * as2[c], q = acc * ad2[c];
#pragma unroll
    for (int off = 8; off >= 1; off >>= 1) {
        p += __shfl_down_sync(0xffffffffu, p, off, 16);
        q += __shfl_down_sync(0xffffffffu, q, off, 16);
    }
    if (c == 0) { g_als2[r] = p; g_ald2[r] = q; }
}

// ---------------- layer 2: aggregation ----------------
__global__ void k_agg2(const float* __restrict__ b2, float* __restrict__ out) {
    int t = threadIdx.x;
    int d = blockIdx.x * 16 + (t >> 4);
    if (d >= NN) return;
    int c = t & 15;
    unsigned hm = 0xFFFFu << (t & 16);
    int cnt = min(g_cnt[d], MAXDEG);
    const int* bucket = g_csr + d * MAXDEG;
    float ald = g_ald2[d];
    float acc = 0.f, den = 0.f;
    for (int i0 = 0; i0 < cnt; i0 += 16) {
        int i = i0 + c;
        int s = (i < cnt) ? bucket[i] : 0;
        int lim = min(16, cnt - i0);
#pragma unroll 8
        for (int j = 0; j < lim; j++) {
            int sj = __shfl_sync(hm, s, j, 16);
            float al = g_als2[sj] + ald;
            al = al > 0.f ? al : NEG_SLOPE * al;
            float w = __expf(al);
            den += w;
            acc = fmaf(w, __half2float(g_h2h[sj * OUTC + c]), acc);
        }
    }
    out[d * OUTC + c] = acc / den + b2[c];
}

// ---------------- launch ----------------
extern "C" void kernel_launch(void* const* d_in, const int* in_sizes, int n_in,
                              void* d_out, int out_size) {
    const float* x   = (const float*)d_in[0];
    const int*   ei  = (const int*)d_in[1];
    const float* W1  = (const float*)d_in[2];
    const float* as1 = (const float*)d_in[3];
    const float* ad1 = (const float*)d_in[4];
    const float* b1  = (const float*)d_in[5];
    const float* W2  = (const float*)d_in[6];
    const float* as2 = (const float*)d_in[7];
    const float* ad2 = (const float*)d_in[8];
    const float* b2  = (const float*)d_in[9];
    float* out = (float*)d_out;

    cudaFuncSetAttribute(k_gemm1, cudaFuncAttributeMaxDynamicSharedMemorySize, SMEM_TOTAL);

    k_init<<<(NN + 255) / 256, 256>>>(W1);
    k_fill<<<(EE / 4 + 255) / 256, 256>>>(ei);
    k_gemm1<<<(NN + ROWS_PER_BLK - 1) / ROWS_PER_BLK, 256, SMEM_TOTAL>>>(x, as1, ad1);
    k_w<<<NN, 256>>>();
    k_agg1<<<(NN + 7) / 8, 256>>>(b1);
    k_gemm2<<<(NN + 15) / 16, 256>>>(W2, as2, ad2);
    k_agg2<<<(NN + 15) / 16, 256>>>(b2, out);
}

// round 17
// speedup vs baseline: 1.3978x; 1.3978x over previous
#include <cuda_runtime.h>
#include <cuda_fp16.h>
#include <mma.h>
#include <math.h>

using namespace nvcuda;

#define NN 50000
#define EE 800000
#define F1 128
#define HEADS 8
#define HID 16
#define OUTC 16
#define NEG_SLOPE 0.2f
#define MAXDEG 64

#define LDA 136
#define LDB 136
#define LDC 132
#define ROWS_PER_BLK 64
#define SMEM_B_BYTES (F1 * LDB * 2)
#define SMEM_AC_BYTES (ROWS_PER_BLK * LDC * 4)
#define SMEM_TOTAL (SMEM_B_BYTES + SMEM_AC_BYTES)

__device__ __forceinline__ int pack_h2(float a, float b) {
    __half2 h = __floats2half2_rn(a, b);
    return *(int*)&h;
}

// ---------------- scratch ----------------
__device__ __align__(16) __half g_h1h[NN * F1];
__device__ __align__(16) float  g_out1[NN * F1];
__device__ __align__(16) float g_als1[NN * HEADS];
__device__ __align__(16) float g_ald1[NN * HEADS];
__device__ __align__(16) __half g_h2h[NN * OUTC];
__device__ float g_als2[NN];
__device__ float g_ald2[NN];
__device__ int   g_cnt[NN];
__device__ int   g_csr[NN * MAXDEG];
__device__ __align__(16) __half g_W1h[F1 * F1];

// ---------------- init ----------------
__global__ void k_init(const float* __restrict__ W1) {
    int i = blockIdx.x * blockDim.x + threadIdx.x;
    if (i < F1 * F1) g_W1h[i] = __float2half(W1[i]);
    if (i < NN) {
        g_cnt[i] = 1;
        g_csr[i * MAXDEG] = i;
    }
}

__global__ void k_fill(const int* __restrict__ ei) {
    int base = (blockIdx.x * blockDim.x + threadIdx.x) * 4;
    if (base >= EE) return;
#pragma unroll
    for (int k = 0; k < 4; k++) {
        int e = base + k;
        if (e < EE) {
            int s = ei[e], d = ei[EE + e];
            int pos = atomicAdd(&g_cnt[d], 1);
            if (pos < MAXDEG) g_csr[d * MAXDEG + pos] = s;
        }
    }
}

// ---------------- layer 1: wmma GEMM + cheap epilogue ----------------
__global__ void __launch_bounds__(256) k_gemm1(const float* __restrict__ x,
                                               const float* __restrict__ as1,
                                               const float* __restrict__ ad1) {
    extern __shared__ __align__(16) char dsm[];
    __half* Bs = (__half*)dsm;
    char* ACbuf = dsm + SMEM_B_BYTES;
    __half* As = (__half*)ACbuf;
    float*  Cs = (float*)ACbuf;
    __shared__ float s_as[F1], s_ad[F1];

    int t = threadIdx.x;
    int rows = blockIdx.x * ROWS_PER_BLK;

    if (t < F1) s_as[t] = as1[t];
    else        s_ad[t - F1] = ad1[t - F1];

#pragma unroll
    for (int i = 0; i < 8; i++) {
        int idx = t + 256 * i;
        int le  = idx * 4;
        int r   = le >> 7;
        int c   = le & 127;
        float4 f = {0.f, 0.f, 0.f, 0.f};
        if (rows + r < NN) f = ((const float4*)x)[rows * 32 + idx];
        __half2* dst = (__half2*)(As + r * LDA + c);
        dst[0] = __floats2half2_rn(f.x, f.y);
        dst[1] = __floats2half2_rn(f.z, f.w);
    }
#pragma unroll
    for (int i = 0; i < 8; i++) {
        int idx = t + 256 * i;
        int le  = idx * 8;
        int k   = le >> 7;
        int n   = le & 127;
        *(int4*)(Bs + k * LDB + n) = ((const int4*)g_W1h)[idx];
    }
    __syncthreads();

    int w = t >> 5;
    wmma::fragment<wmma::accumulator, 16, 16, 16, float> c0, c1, c2, c3;
    wmma::fill_fragment(c0, 0.f);
    wmma::fill_fragment(c1, 0.f);
    wmma::fill_fragment(c2, 0.f);
    wmma::fill_fragment(c3, 0.f);
#pragma unroll
    for (int k = 0; k < 8; k++) {
        wmma::fragment<wmma::matrix_a, 16, 16, 16, __half, wmma::row_major> a0, a1, a2, a3;
        wmma::fragment<wmma::matrix_b, 16, 16, 16, __half, wmma::row_major> b;
        wmma::load_matrix_sync(b, Bs + (k * 16) * LDB + w * 16, LDB);
        wmma::load_matrix_sync(a0, As + (0 * 16) * LDA + k * 16, LDA);
        wmma::load_matrix_sync(a1, As + (1 * 16) * LDA + k * 16, LDA);
        wmma::load_matrix_sync(a2, As + (2 * 16) * LDA + k * 16, LDA);
        wmma::load_matrix_sync(a3, As + (3 * 16) * LDA + k * 16, LDA);
        wmma::mma_sync(c0, a0, b, c0);
        wmma::mma_sync(c1, a1, b, c1);
        wmma::mma_sync(c2, a2, b, c2);
        wmma::mma_sync(c3, a3, b, c3);
    }
    __syncthreads();
    wmma::store_matrix_sync(Cs + (0 * 16) * LDC + w * 16, c0, LDC, wmma::mem_row_major);
    wmma::store_matrix_sync(Cs + (1 * 16) * LDC + w * 16, c1, LDC, wmma::mem_row_major);
    wmma::store_matrix_sync(Cs + (2 * 16) * LDC + w * 16, c2, LDC, wmma::mem_row_major);
    wmma::store_matrix_sync(Cs + (3 * 16) * LDC + w * 16, c3, LDC, wmma::mem_row_major);
    __syncthreads();

    {
        int row = t >> 2;
        int col0 = (t & 3) * 32;
        int grow = rows + row;
        if (grow < NN) {
            const float* src = Cs + row * LDC + col0;
            __half* dst = g_h1h + grow * F1 + col0;
#pragma unroll
            for (int i = 0; i < 4; i++) {
                float4 a = *(const float4*)(src + i * 8);
                float4 b = *(const float4*)(src + i * 8 + 4);
                int4 pk;
                pk.x = pack_h2(a.x, a.y);
                pk.y = pack_h2(a.z, a.w);
                pk.z = pack_h2(b.x, b.y);
                pk.w = pack_h2(b.z, b.w);
                *(int4*)(dst + i * 8) = pk;
            }
        }
    }

#pragma unroll
    for (int pp = 0; pp < 2; pp++) {
        int pair = t + pp * 256;
        int row = pair >> 3, h = pair & 7;
        int grow = rows + row;
        const float* cr = Cs + row * LDC + h * 16;
        const float* av = s_as + h * 16;
        const float* dv = s_ad + h * 16;
        float p = 0.f, q = 0.f;
#pragma unroll
        for (int i = 0; i < 4; i++) {
            float4 v = *(const float4*)(cr + i * 4);
            float4 a = *(const float4*)(av + i * 4);
            float4 dd = *(const float4*)(dv + i * 4);
            p = fmaf(v.x, a.x, p);  q = fmaf(v.x, dd.x, q);
            p = fmaf(v.y, a.y, p);  q = fmaf(v.y, dd.y, q);
            p = fmaf(v.z, a.z, p);  q = fmaf(v.z, dd.z, q);
            p = fmaf(v.w, a.w, p);  q = fmaf(v.w, dd.w, q);
        }
        if (grow < NN) {
            g_als1[grow * HEADS + h] = p;
            g_ald1[grow * HEADS + h] = q;
        }
    }
}

// ---------------- layer 1: fused weights(smem) + aggregation, 8 nodes/block ----------------
// Phase 1: 256 threads compute 8 nodes x 64 slots x 8 heads weights into smem.
// Phase 2: warp per node, branch-free gather with inline den accumulation.
__global__ void __launch_bounds__(256) k_agg1(const float* __restrict__ b1) {
    __shared__ __half wsm[8][MAXDEG][HEADS];   // 8KB
    __shared__ float s_ald[8][HEADS];
    int t = threadIdx.x;
    int nb = blockIdx.x * 8;                   // NN % 8 == 0

    if (t < 64) {
        s_ald[t >> 3][t & 7] = g_ald1[(nb + (t >> 3)) * HEADS + (t & 7)];
    }
    __syncthreads();

    // phase 1: 512 (node,slot) pairs, 2 per thread
#pragma unroll
    for (int pp = 0; pp < 2; pp++) {
        int pair = t + pp * 256;
        int nl = pair >> 6, slot = pair & 63;
        int d = nb + nl;
        float w0 = 0.f, w1 = 0.f, w2 = 0.f, w3 = 0.f, w4 = 0.f, w5 = 0.f, w6 = 0.f, w7 = 0.f;
        int cnt = min(g_cnt[d], MAXDEG);
        if (slot < cnt) {
            int src = g_csr[d * MAXDEG + slot];
            float4 a0 = *(const float4*)(g_als1 + src * HEADS);
            float4 a1 = *(const float4*)(g_als1 + src * HEADS + 4);
            float v;
            v = a0.x + s_ald[nl][0]; v = fmaxf(v, NEG_SLOPE * v); w0 = __expf(v);
            v = a0.y + s_ald[nl][1]; v = fmaxf(v, NEG_SLOPE * v); w1 = __expf(v);
            v = a0.z + s_ald[nl][2]; v = fmaxf(v, NEG_SLOPE * v); w2 = __expf(v);
            v = a0.w + s_ald[nl][3]; v = fmaxf(v, NEG_SLOPE * v); w3 = __expf(v);
            v = a1.x + s_ald[nl][4]; v = fmaxf(v, NEG_SLOPE * v); w4 = __expf(v);
            v = a1.y + s_ald[nl][5]; v = fmaxf(v, NEG_SLOPE * v); w5 = __expf(v);
            v = a1.z + s_ald[nl][6]; v = fmaxf(v, NEG_SLOPE * v); w6 = __expf(v);
            v = a1.w + s_ald[nl][7]; v = fmaxf(v, NEG_SLOPE * v); w7 = __expf(v);
        }
        int4 pk;
        pk.x = pack_h2(w0, w1);
        pk.y = pack_h2(w2, w3);
        pk.z = pack_h2(w4, w5);
        pk.w = pack_h2(w6, w7);
        *(int4*)&wsm[nl][slot][0] = pk;
    }
    __syncthreads();

    // phase 2: warp per node
    int warp = t >> 5;
    int lane = t & 31;
    int d = nb + warp;
    int h = lane >> 2;
    int cnt = min(g_cnt[d], MAXDEG);
    int cnt16 = (cnt + 15) & ~15;
    const int* bucket = g_csr + d * MAXDEG;
    const __half* hbase = g_h1h + lane * 4;
    float4 acc = {0.f, 0.f, 0.f, 0.f};
    float den = 0.f;
    for (int i0 = 0; i0 < cnt16; i0 += 16) {
        int s = bucket[i0 + (lane & 15)];
#pragma unroll
        for (int j = 0; j < 16; j++) {
            int sj = __shfl_sync(0xffffffffu, s, j);
            unsigned su = min((unsigned)sj, (unsigned)(NN - 1));  // padded slots have w=0
            float w = __half2float(wsm[warp][i0 + j][h]);
            den += w;
            uint2 hv = *(const uint2*)(hbase + ((size_t)su << 7));
            float2 f0 = __half22float2(*(const __half2*)&hv.x);
            float2 f1 = __half22float2(*(const __half2*)&hv.y);
            acc.x = fmaf(w, f0.x, acc.x);
            acc.y = fmaf(w, f0.y, acc.y);
            acc.z = fmaf(w, f1.x, acc.z);
            acc.w = fmaf(w, f1.y, acc.w);
        }
    }
    float inv = 1.f / den;
    float4 bv = *(const float4*)(b1 + lane * 4);
    float4 o;
    o.x = acc.x * inv + bv.x;
    o.y = acc.y * inv + bv.y;
    o.z = acc.z * inv + bv.z;
    o.w = acc.w * inv + bv.w;
    o.x = o.x > 0.f ? o.x : expm1f(o.x);
    o.y = o.y > 0.f ? o.y : expm1f(o.y);
    o.z = o.z > 0.f ? o.z : expm1f(o.z);
    o.w = o.w > 0.f ? o.w : expm1f(o.w);
    *(float4*)(g_out1 + d * F1 + lane * 4) = o;
}

// ---------------- layer 2: GEMM ----------------
__global__ void k_gemm2(const float* __restrict__ W2,
                        const float* __restrict__ as2, const float* __restrict__ ad2) {
    int t = threadIdx.x;
    int rbase = blockIdx.x * 16;
    __shared__ float4 sh[16][32];
    __shared__ float ws[F1][OUTC];
    const float4* src = (const float4*)(g_out1 + rbase * F1);
    ((float4*)sh)[t]       = src[t];
    ((float4*)sh)[t + 256] = src[t + 256];
#pragma unroll
    for (int i = t; i < F1 * OUTC; i += 256) ws[i >> 4][i & 15] = W2[i];
    __syncthreads();
    int r_loc = t >> 4, c = t & 15;
    float acc = 0.f;
#pragma unroll 8
    for (int k4 = 0; k4 < 32; k4++) {
        float4 hv = sh[r_loc][k4];
        acc = fmaf(hv.x, ws[k4 * 4 + 0][c], acc);
        acc = fmaf(hv.y, ws[k4 * 4 + 1][c], acc);
        acc = fmaf(hv.z, ws[k4 * 4 + 2][c], acc);
        acc = fmaf(hv.w, ws[k4 * 4 + 3][c], acc);
    }
    int r = rbase + r_loc;
    g_h2h[r * OUTC + c] = __float2half(acc);
    float p = acc * as2[c], q = acc * ad2[c];
#pragma unroll
    for (int off = 8; off >= 1; off >>= 1) {
        p += __shfl_down_sync(0xffffffffu, p, off, 16);
        q += __shfl_down_sync(0xffffffffu, q, off, 16);
    }
    if (c == 0) { g_als2[r] = p; g_ald2[r] = q; }
}

// ---------------- layer 2: aggregation ----------------
__global__ void k_agg2(const float* __restrict__ b2, float* __restrict__ out) {
    int t = threadIdx.x;
    int d = blockIdx.x * 16 + (t >> 4);
    if (d >= NN) return;
    int c = t & 15;
    unsigned hm = 0xFFFFu << (t & 16);
    int cnt = min(g_cnt[d], MAXDEG);
    const int* bucket = g_csr + d * MAXDEG;
    float ald = g_ald2[d];
    float acc = 0.f, den = 0.f;
    for (int i0 = 0; i0 < cnt; i0 += 16) {
        int i = i0 + c;
        int s = (i < cnt) ? bucket[i] : 0;
        int lim = min(16, cnt - i0);
#pragma unroll 8
        for (int j = 0; j < lim; j++) {
            int sj = __shfl_sync(hm, s, j, 16);
            float al = g_als2[sj] + ald;
            al = al > 0.f ? al : NEG_SLOPE * al;
            float w = __expf(al);
            den += w;
            acc = fmaf(w, __half2float(g_h2h[sj * OUTC + c]), acc);
        }
    }
    out[d * OUTC + c] = acc / den + b2[c];
}

// ---------------- launch ----------------
extern "C" void kernel_launch(void* const* d_in, const int* in_sizes, int n_in,
                              void* d_out, int out_size) {
    const float* x   = (const float*)d_in[0];
    const int*   ei  = (const int*)d_in[1];
    const float* W1  = (const float*)d_in[2];
    const float* as1 = (const float*)d_in[3];
    const float* ad1 = (const float*)d_in[4];
    const float* b1  = (const float*)d_in[5];
    const float* W2  = (const float*)d_in[6];
    const float* as2 = (const float*)d_in[7];
    const float* ad2 = (const float*)d_in[8];
    const float* b2  = (const float*)d_in[9];
    float* out = (float*)d_out;

    cudaFuncSetAttribute(k_gemm1, cudaFuncAttributeMaxDynamicSharedMemorySize, SMEM_TOTAL);

    k_init<<<(NN + 255) / 256, 256>>>(W1);
    k_fill<<<(EE / 4 + 255) / 256, 256>>>(ei);
    k_gemm1<<<(NN + ROWS_PER_BLK - 1) / ROWS_PER_BLK, 256, SMEM_TOTAL>>>(x, as1, ad1);
    k_agg1<<<NN / 8, 256>>>(b1);
    k_gemm2<<<(NN + 15) / 16, 256>>>(W2, as2, ad2);
    k_agg2<<<(NN + 15) / 16, 256>>>(b2, out);
}